// round 1
// baseline (speedup 1.0000x reference)
#include <cuda_runtime.h>

// SparseTopKLayer: out = x + (x*rms*w) * mask * gamma
//   rms = rsqrt(mean(x^2) + 1e-6), mask = |x*rms*w| >= kth_largest(|x*rms*w|, k)
// One CTA per row. D = 2048, 256 threads, 8 values/thread in registers.
// Exact k-th largest via MSB-first 8-bit radix select on float bits
// (non-negative floats compare as uints), warp-aggregated smem histogram.

constexpr int D = 2048;
constexpr int T = 256;

__global__ void __launch_bounds__(T) sparse_topk_kernel(
    const float* __restrict__ x,
    const float* __restrict__ w,
    const float* __restrict__ g,
    const int* __restrict__ kptr,
    float* __restrict__ out)
{
    const int row = blockIdx.x;
    const int t   = threadIdx.x;

    const float4* xr = reinterpret_cast<const float4*>(x) + (size_t)row * (D / 4);
    float4 xa = xr[t];
    float4 xb = xr[t + T];

    // ---- sum of squares -> rms ----
    float ss = xa.x*xa.x + xa.y*xa.y + xa.z*xa.z + xa.w*xa.w
             + xb.x*xb.x + xb.y*xb.y + xb.z*xb.z + xb.w*xb.w;
    #pragma unroll
    for (int o = 16; o > 0; o >>= 1) ss += __shfl_xor_sync(0xffffffffu, ss, o);

    __shared__ float warp_s[8];
    __shared__ float rms_sh;
    if ((t & 31) == 0) warp_s[t >> 5] = ss;
    __syncthreads();
    if (t < 8) {
        float v = warp_s[t];
        #pragma unroll
        for (int o = 4; o > 0; o >>= 1) v += __shfl_xor_sync(0xffu, v, o);
        if (t == 0) rms_sh = rsqrtf(v * (1.0f / (float)D) + 1e-6f);
    }
    __syncthreads();
    const float rms = rms_sh;

    // ---- weight / gamma (L2-resident broadcast) ----
    const float4* wv = reinterpret_cast<const float4*>(w);
    const float4* gv = reinterpret_cast<const float4*>(g);
    float4 wa = wv[t], wb = wv[t + T];
    float4 ga = gv[t], gb = gv[t + T];

    float xv[8] = {xa.x, xa.y, xa.z, xa.w, xb.x, xb.y, xb.z, xb.w};
    float wf[8] = {wa.x, wa.y, wa.z, wa.w, wb.x, wb.y, wb.z, wb.w};
    float gf[8] = {ga.x, ga.y, ga.z, ga.w, gb.x, gb.y, gb.z, gb.w};

    unsigned mb[8];   // |x*rms*w| as ordered uint bits
    float    wg[8];   // w * gamma
    #pragma unroll
    for (int i = 0; i < 8; i++) {
        float xn = (xv[i] * rms) * wf[i];
        mb[i] = __float_as_uint(fabsf(xn));
        wg[i] = wf[i] * gf[i];
    }

    // ---- exact k-th largest via radix select ----
    __shared__ unsigned hist[256];
    __shared__ unsigned scan[256];
    __shared__ unsigned sel_b, sel_above, thr_sh;

    int remaining = *kptr;
    unsigned prefix = 0u, pmask = 0u;
    unsigned thr = 0u;

    #pragma unroll 1
    for (int shift = 24; shift >= 0; shift -= 8) {
        hist[t] = 0u;
        __syncthreads();

        // warp-aggregated histogram of candidate values
        #pragma unroll
        for (int i = 0; i < 8; i++) {
            bool m = (mb[i] & pmask) == prefix;
            unsigned b = (mb[i] >> shift) & 255u;
            unsigned key = m ? b : 0xFFFFFFFFu;
            unsigned grp = __match_any_sync(0xffffffffu, key);
            if (m) {
                int leader = __ffs(grp) - 1;
                if ((int)(t & 31) == leader)
                    atomicAdd(&hist[b], (unsigned)__popc(grp));
            }
        }
        __syncthreads();

        // inclusive suffix sums (Hillis-Steele, descending)
        scan[t] = hist[t];
        __syncthreads();
        #pragma unroll
        for (int off = 1; off < 256; off <<= 1) {
            unsigned v = scan[t];
            unsigned a = (t + off < 256) ? scan[t + off] : 0u;
            __syncthreads();
            scan[t] = v + a;
            __syncthreads();
        }
        unsigned S  = scan[t];
        unsigned Sn = (t < 255) ? scan[t + 1] : 0u;
        if ((int)S >= remaining && (int)Sn < remaining) {
            sel_b = (unsigned)t;
            sel_above = Sn;
        }
        __syncthreads();

        unsigned b   = sel_b;
        unsigned cnt = hist[b];
        remaining -= (int)sel_above;
        prefix |= (b << shift);
        pmask  |= (0xFFu << shift);
        __syncthreads();  // protect hist[] before next-pass clear

        if ((int)cnt == remaining) {
            // threshold = min of values in selected bucket
            if (t == 0) thr_sh = 0xFFFFFFFFu;
            __syncthreads();
            unsigned lmin = 0xFFFFFFFFu;
            #pragma unroll
            for (int i = 0; i < 8; i++)
                if ((mb[i] & pmask) == prefix) lmin = min(lmin, mb[i]);
            if (lmin != 0xFFFFFFFFu) atomicMin(&thr_sh, lmin);
            __syncthreads();
            thr = thr_sh;
            break;
        }
        if (remaining == 1) {
            // threshold = max of values in selected bucket
            if (t == 0) thr_sh = 0u;
            __syncthreads();
            unsigned lmax = 0u;
            #pragma unroll
            for (int i = 0; i < 8; i++)
                if ((mb[i] & pmask) == prefix) lmax = max(lmax, mb[i]);
            if (lmax != 0u) atomicMax(&thr_sh, lmax);
            __syncthreads();
            thr = thr_sh;
            break;
        }
        if (shift == 0) {
            thr = prefix;  // fully determined
            break;
        }
    }

    // ---- output: x + x*rms*(w*g) where |x*rms*w| >= thr ----
    float fo[8];
    #pragma unroll
    for (int i = 0; i < 8; i++) {
        float add = (xv[i] * rms) * wg[i];
        fo[i] = xv[i] + ((mb[i] >= thr) ? add : 0.0f);
    }

    float4* orow = reinterpret_cast<float4*>(out) + (size_t)row * (D / 4);
    orow[t]     = make_float4(fo[0], fo[1], fo[2], fo[3]);
    orow[t + T] = make_float4(fo[4], fo[5], fo[6], fo[7]);
}

extern "C" void kernel_launch(void* const* d_in, const int* in_sizes, int n_in,
                              void* d_out, int out_size)
{
    const float* x = (const float*)d_in[0];
    const float* w = (const float*)d_in[1];
    const float* g = (const float*)d_in[2];
    const int*   k = (const int*)d_in[3];

    int N = in_sizes[0] / D;   // 32768 rows
    sparse_topk_kernel<<<N, T>>>(x, w, g, k, (float*)d_out);
}

// round 2
// speedup vs baseline: 1.1073x; 1.1073x over previous
#include <cuda_runtime.h>

// SparseTopKLayer: out = x + (x*rms*w) * mask * gamma
//   rms = rsqrt(mean(x^2)+1e-6); mask = |x_norm| >= kth_largest(|x_norm|, k)
// One CTA per row, D=2048, 256 threads, 8 floats/thread in registers.
// Exact k-th largest via MSB-first 8-bit radix select on float bits of |x*w|
// (ordering identical to |x*rms*w| since rms>0 is row-constant).
// Per-warp redundant suffix scan (shuffles only) -> 2 barriers per pass.

constexpr int D = 2048;
constexpr int T = 256;

__global__ void __launch_bounds__(T) sparse_topk_kernel(
    const float* __restrict__ x,
    const float* __restrict__ w,
    const float* __restrict__ g,
    const int* __restrict__ kptr,
    float* __restrict__ out)
{
    const int row  = blockIdx.x;
    const int t    = threadIdx.x;
    const int lane = t & 31;

    __shared__ __align__(16) unsigned hist[2][256];
    __shared__ float warp_s[8];
    __shared__ float rms_sh;
    __shared__ unsigned thr_lo, thr_hi;

    const float4* xr = reinterpret_cast<const float4*>(x) + (size_t)row * (D / 4);
    float4 xa = xr[t];
    float4 xb = xr[t + T];
    const float4* wv = reinterpret_cast<const float4*>(w);
    float4 wa = wv[t], wb = wv[t + T];

    float xv[8] = {xa.x, xa.y, xa.z, xa.w, xb.x, xb.y, xb.z, xb.w};
    float wf[8] = {wa.x, wa.y, wa.z, wa.w, wb.x, wb.y, wb.z, wb.w};
    float xw[8];
    float ss = 0.0f;
    #pragma unroll
    for (int i = 0; i < 8; i++) {
        xw[i] = xv[i] * wf[i];
        ss = fmaf(xv[i], xv[i], ss);
    }

    // warp partial sums of x^2
    #pragma unroll
    for (int o = 16; o > 0; o >>= 1) ss += __shfl_xor_sync(0xffffffffu, ss, o);
    if (lane == 0) warp_s[t >> 5] = ss;
    if (t == 0) { thr_lo = 0xFFFFFFFFu; thr_hi = 0u; }

    int rem = *kptr;                 // uniform broadcast load
    unsigned prefix = 0u, pmask = 0u, thr = 0u;

    #pragma unroll 1
    for (int pass = 0; pass < 4; ++pass) {
        const int shift = 24 - 8 * pass;
        unsigned* h = hist[pass & 1];
        h[t] = 0u;                   // buffer last touched 2 passes ago -> safe
        __syncthreads();

        // warp-aggregated histogram of candidates
        #pragma unroll
        for (int i = 0; i < 8; i++) {
            unsigned u = __float_as_uint(xw[i]) & 0x7FFFFFFFu;
            bool m = (u & pmask) == prefix;
            unsigned b = (u >> shift) & 255u;
            unsigned grp = __match_any_sync(0xffffffffu, m ? b : 0xFFFFFFFFu);
            if (m && lane == __ffs(grp) - 1)
                atomicAdd(&h[b], (unsigned)__popc(grp));
        }
        // fold rms finalize into pass 0 (hidden under histogram)
        if (pass == 0 && t < 8) {
            float v = warp_s[t];
            #pragma unroll
            for (int o = 4; o > 0; o >>= 1) v += __shfl_xor_sync(0xffu, v, o);
            if (t == 0) rms_sh = rsqrtf(v * (1.0f / (float)D) + 1e-6f);
        }
        __syncthreads();

        // per-warp redundant suffix scan over 256 bins (no barriers)
        uint4 h0 = *reinterpret_cast<const uint4*>(&h[lane * 8]);
        uint4 h1 = *reinterpret_cast<const uint4*>(&h[lane * 8 + 4]);
        unsigned hr[8] = {h0.x, h0.y, h0.z, h0.w, h1.x, h1.y, h1.z, h1.w};
        unsigned s = 0;
        #pragma unroll
        for (int j = 0; j < 8; j++) s += hr[j];
        unsigned S = s;
        #pragma unroll
        for (int o = 1; o < 32; o <<= 1) {
            unsigned v = __shfl_down_sync(0xffffffffu, S, o);
            if (lane + o < 32) S += v;   // inclusive suffix sum of lane blocks
        }
        unsigned suf = S - s;            // suffix just above my 8-bin block
        int bj = -1; unsigned cnt = 0, abv = 0;
        #pragma unroll
        for (int j = 7; j >= 0; j--) {
            unsigned ns = suf + hr[j];
            if (ns >= (unsigned)rem && suf < (unsigned)rem) { bj = j; cnt = hr[j]; abv = suf; }
            suf = ns;
        }
        unsigned bal = __ballot_sync(0xffffffffu, bj >= 0);
        int src = __ffs(bal) - 1;        // exactly one lane found the bucket
        unsigned B = __shfl_sync(0xffffffffu, (unsigned)(lane * 8 + bj), src);
        cnt = __shfl_sync(0xffffffffu, cnt, src);
        abv = __shfl_sync(0xffffffffu, abv, src);

        rem -= (int)abv;
        prefix |= B << shift;
        pmask  |= 255u << shift;

        if ((int)cnt == rem) {           // threshold = min of bucket candidates
            unsigned lmin = 0xFFFFFFFFu;
            #pragma unroll
            for (int i = 0; i < 8; i++) {
                unsigned u = __float_as_uint(xw[i]) & 0x7FFFFFFFu;
                if ((u & pmask) == prefix) lmin = min(lmin, u);
            }
            #pragma unroll
            for (int o = 16; o > 0; o >>= 1)
                lmin = min(lmin, __shfl_xor_sync(0xffffffffu, lmin, o));
            if (lane == 0) atomicMin(&thr_lo, lmin);
            __syncthreads();
            thr = thr_lo;
            break;
        }
        if (rem == 1) {                  // threshold = max of bucket candidates
            unsigned lmax = 0u;
            #pragma unroll
            for (int i = 0; i < 8; i++) {
                unsigned u = __float_as_uint(xw[i]) & 0x7FFFFFFFu;
                if ((u & pmask) == prefix) lmax = max(lmax, u);
            }
            #pragma unroll
            for (int o = 16; o > 0; o >>= 1)
                lmax = max(lmax, __shfl_xor_sync(0xffffffffu, lmax, o));
            if (lane == 0) atomicMax(&thr_hi, lmax);
            __syncthreads();
            thr = thr_hi;
            break;
        }
        if (shift == 0) { thr = prefix; break; }
    }

    // epilogue: out = x + (x*w*rms)*g where |x*w| >= thr
    const float4* gv = reinterpret_cast<const float4*>(g);
    float4 ga = gv[t], gb = gv[t + T];
    float gf[8] = {ga.x, ga.y, ga.z, ga.w, gb.x, gb.y, gb.z, gb.w};
    const float rms  = rms_sh;
    const float thrf = __uint_as_float(thr);

    float fo[8];
    #pragma unroll
    for (int i = 0; i < 8; i++) {
        float add = (xw[i] * rms) * gf[i];
        fo[i] = xv[i] + ((fabsf(xw[i]) >= thrf) ? add : 0.0f);
    }

    float4* orow = reinterpret_cast<float4*>(out) + (size_t)row * (D / 4);
    orow[t]     = make_float4(fo[0], fo[1], fo[2], fo[3]);
    orow[t + T] = make_float4(fo[4], fo[5], fo[6], fo[7]);
}

extern "C" void kernel_launch(void* const* d_in, const int* in_sizes, int n_in,
                              void* d_out, int out_size)
{
    const float* x = (const float*)d_in[0];
    const float* w = (const float*)d_in[1];
    const float* g = (const float*)d_in[2];
    const int*   k = (const int*)d_in[3];

    int N = in_sizes[0] / D;   // 32768 rows
    sparse_topk_kernel<<<N, T>>>(x, w, g, k, (float*)d_out);
}

// round 3
// speedup vs baseline: 2.8810x; 2.6019x over previous
#include <cuda_runtime.h>

// SparseTopKLayer: out = x + ((x*rms)*w)*mask*gamma
//   rms = rsqrt(mean(x^2)+1e-6); mask = |x_norm| >= kth_largest(|x_norm|, k)
// Rank on |x*w| (rms>0 row-constant -> identical ordering).
// One CTA per row, 256 threads, 8 elems/thread in registers.
// Exact threshold via: Gaussian-quantile bracket (1 count pass) +
// adaptive-window 128-bin histogram select on the ~128 bracket candidates.
// Generic fallback (bracket miss / weird data) stays exact via 3-way
// re-bracketing and window narrowing to width 1.

constexpr int D    = 2048;
constexpr int T    = 256;
constexpr int BINS = 128;

__device__ __forceinline__ float inv_phi_tail(float q) {
    // Phi^{-1}(1-q), q in (0, 0.5]; Abramowitz-Stegun 26.2.23, |err|<4.5e-4
    q = fminf(fmaxf(q, 1e-7f), 0.4999f);
    float s = sqrtf(-2.0f * __logf(q));
    return s - (2.30753f + 0.27061f * s) / (1.0f + s * (0.99229f + 0.04481f * s));
}

__global__ void __launch_bounds__(T) sparse_topk_kernel(
    const float* __restrict__ x,
    const float* __restrict__ w,
    const float* __restrict__ g,
    const int* __restrict__ kptr,
    float* __restrict__ out)
{
    const int row  = blockIdx.x;
    const int t    = threadIdx.x;
    const int lane = t & 31;
    const int wid  = t >> 5;

    __shared__ float2   red[8];
    __shared__ __align__(16) unsigned hist[2][BINS];
    __shared__ int      cntLo[8], cntHi[8];
    __shared__ unsigned b1_sh, b2_sh, lo_sh, hi_sh, thr_sh, thrmin_sh, thrmax_sh;
    __shared__ int      r_sh, mode_sh;
    __shared__ float    rms_sh;

    // ---- load row + weight, derive |x*w| bits, dual sums ----
    const float4* xr = reinterpret_cast<const float4*>(x) + (size_t)row * (D / 4);
    const float4* wv = reinterpret_cast<const float4*>(w);
    float4 xa = xr[t], xb = xr[t + T];
    float4 wa = wv[t], wb = wv[t + T];

    float xv[8] = {xa.x, xa.y, xa.z, xa.w, xb.x, xb.y, xb.z, xb.w};
    float wf[8] = {wa.x, wa.y, wa.z, wa.w, wb.x, wb.y, wb.z, wb.w};
    unsigned u[8];
    float ss = 0.0f, sw = 0.0f;
    #pragma unroll
    for (int i = 0; i < 8; i++) {
        float xwv = xv[i] * wf[i];
        u[i] = __float_as_uint(xwv) & 0x7FFFFFFFu;
        ss = fmaf(xv[i], xv[i], ss);
        sw = fmaf(xwv, xwv, sw);
    }
    #pragma unroll
    for (int o = 16; o > 0; o >>= 1) {
        ss += __shfl_xor_sync(0xffffffffu, ss, o);
        sw += __shfl_xor_sync(0xffffffffu, sw, o);
    }
    if (lane == 0) red[wid] = make_float2(ss, sw);
    if (t < 2 * BINS) ((unsigned*)hist)[t] = 0u;
    if (t == 0) { thrmin_sh = 0xFFFFFFFFu; thrmax_sh = 0u; }
    __syncthreads();

    // ---- warp0: rms + quantile-bracket pivots ----
    if (t < 8) {
        float2 v = red[t];
        #pragma unroll
        for (int o = 4; o > 0; o >>= 1) {
            v.x += __shfl_xor_sync(0xffu, v.x, o);
            v.y += __shfl_xor_sync(0xffu, v.y, o);
        }
        if (t == 0) {
            rms_sh = rsqrtf(v.x * (1.0f / (float)D) + 1e-6f);
            float sigma = sqrtf(v.y * (1.0f / (float)D));
            int k = *kptr;
            float t1 = inv_phi_tail((float)(k + 64) * (0.5f / (float)D));
            float t2 = inv_phi_tail((float)(k - 64 > 1 ? k - 64 : 1) * (0.5f / (float)D));
            unsigned b1 = (t1 > 0.0f) ? __float_as_uint(t1 * sigma) : 0u;
            unsigned b2 = __float_as_uint(fmaxf(t2, 0.0f) * sigma);
            if (b2 <= b1) b2 = b1 + 1u;
            b1_sh = b1; b2_sh = b2;
        }
    }
    __syncthreads();

    // ---- exact counts at the two brackets ----
    {
        unsigned b1 = b1_sh, b2 = b2_sh;
        unsigned c1 = 0, c2 = 0;
        #pragma unroll
        for (int i = 0; i < 8; i++) {
            c1 += (u[i] >= b1);
            c2 += (u[i] >= b2);
        }
        c1 = __reduce_add_sync(0xffffffffu, c1);
        c2 = __reduce_add_sync(0xffffffffu, c2);
        if (lane == 0) { cntLo[wid] = (int)c1; cntHi[wid] = (int)c2; }
    }
    __syncthreads();
    if (t == 0) {
        int cLo = 0, cHi = 0;
        #pragma unroll
        for (int j = 0; j < 8; j++) { cLo += cntLo[j]; cHi += cntHi[j]; }
        int k = *kptr;
        unsigned lo, hi; int r;
        if (cHi >= k)      { lo = b2_sh; hi = 0x80000000u; r = k; }
        else if (cLo >= k) { lo = b1_sh; hi = b2_sh;       r = k - cHi; }
        else               { lo = 0u;    hi = b1_sh;       r = k - cLo; }
        lo_sh = lo; hi_sh = hi; r_sh = r; mode_sh = 0;
    }
    __syncthreads();

    // ---- adaptive-window histogram select ----
    unsigned thr = 0u;
    int p = 0;
    while (true) {
        unsigned lo = lo_sh, hi = hi_sh;
        unsigned range = hi - lo;
        int s = (range > (unsigned)BINS) ? (25 - __clz(range - 1u)) : 0;
        unsigned* h = hist[p];
        #pragma unroll
        for (int i = 0; i < 8; i++) {
            unsigned d = u[i] - lo;
            if (d < range) atomicAdd(&h[d >> s], 1u);
        }
        if (t < BINS) hist[p ^ 1][t] = 0u;   // prep next round's buffer
        __syncthreads();

        if (t < 32) {   // warp0: suffix scan + bucket pick + publish
            uint4 hv = *reinterpret_cast<const uint4*>(&h[lane * 4]);
            unsigned hr[4] = {hv.x, hv.y, hv.z, hv.w};
            unsigned bs = hr[0] + hr[1] + hr[2] + hr[3];
            unsigned S = bs;
            #pragma unroll
            for (int o = 1; o < 32; o <<= 1) {
                unsigned v = __shfl_down_sync(0xffffffffu, S, o);
                if (lane + o < 32) S += v;
            }
            unsigned suf = S - bs;          // count in strictly-higher lanes
            int r = r_sh;
            int bj = -1; unsigned cnt = 0, abv = 0;
            #pragma unroll
            for (int j = 3; j >= 0; j--) {
                unsigned ns = suf + hr[j];
                if (suf < (unsigned)r && ns >= (unsigned)r) { bj = j; cnt = hr[j]; abv = suf; }
                suf = ns;
            }
            unsigned bal = __ballot_sync(0xffffffffu, bj >= 0);
            if (bal) {
                int src = __ffs(bal) - 1;
                unsigned B = __shfl_sync(0xffffffffu, (unsigned)(lane * 4 + bj), src);
                cnt = __shfl_sync(0xffffffffu, cnt, src);
                abv = __shfl_sync(0xffffffffu, abv, src);
                if (lane == 0) {
                    int r2 = r - (int)abv;
                    unsigned nlo = lo + (B << s);
                    unsigned nhi = lo + ((B + 1u) << s);
                    if (nhi > hi) nhi = hi;
                    lo_sh = nlo; hi_sh = nhi; r_sh = r2;
                    if (s == 0)              { mode_sh = 1; thr_sh = nlo; }
                    else if ((int)cnt == r2) { mode_sh = 2; }   // thr = min in bucket
                    else if (r2 == 1)        { mode_sh = 3; }   // thr = max in bucket
                    else                     { mode_sh = 0; }
                }
            } else if (lane == 0) { mode_sh = 1; thr_sh = lo; }  // defensive
        }
        __syncthreads();

        int m = mode_sh;
        if (m == 1) { thr = thr_sh; break; }
        if (m >= 2) {
            unsigned nlo = lo_sh, nrange = hi_sh - lo_sh;
            if (m == 2) {
                unsigned lm = 0xFFFFFFFFu;
                #pragma unroll
                for (int i = 0; i < 8; i++) {
                    unsigned d = u[i] - nlo;
                    if (d < nrange) lm = min(lm, u[i]);
                }
                #pragma unroll
                for (int o = 16; o > 0; o >>= 1)
                    lm = min(lm, __shfl_xor_sync(0xffffffffu, lm, o));
                if (lane == 0) atomicMin(&thrmin_sh, lm);
            } else {
                unsigned lm = 0u;
                #pragma unroll
                for (int i = 0; i < 8; i++) {
                    unsigned d = u[i] - nlo;
                    if (d < nrange) lm = max(lm, u[i]);
                }
                #pragma unroll
                for (int o = 16; o > 0; o >>= 1)
                    lm = max(lm, __shfl_xor_sync(0xffffffffu, lm, o));
                if (lane == 0) atomicMax(&thrmax_sh, lm);
            }
            __syncthreads();
            thr = (m == 2) ? thrmin_sh : thrmax_sh;
            break;
        }
        p ^= 1;
    }

    // ---- epilogue ----
    const float4* gv = reinterpret_cast<const float4*>(g);
    float4 ga = gv[t], gb = gv[t + T];
    float gf[8] = {ga.x, ga.y, ga.z, ga.w, gb.x, gb.y, gb.z, gb.w};
    const float rms = rms_sh;

    float fo[8];
    #pragma unroll
    for (int i = 0; i < 8; i++) {
        float add = ((xv[i] * rms) * wf[i]) * gf[i];
        fo[i] = xv[i] + ((u[i] >= thr) ? add : 0.0f);
    }
    float4* orow = reinterpret_cast<float4*>(out) + (size_t)row * (D / 4);
    orow[t]     = make_float4(fo[0], fo[1], fo[2], fo[3]);
    orow[t + T] = make_float4(fo[4], fo[5], fo[6], fo[7]);
}

extern "C" void kernel_launch(void* const* d_in, const int* in_sizes, int n_in,
                              void* d_out, int out_size)
{
    const float* x = (const float*)d_in[0];
    const float* w = (const float*)d_in[1];
    const float* g = (const float*)d_in[2];
    const int*   k = (const int*)d_in[3];

    int N = in_sizes[0] / D;   // 32768 rows
    sparse_topk_kernel<<<N, T>>>(x, w, g, k, (float*)d_out);
}

// round 5
// speedup vs baseline: 3.2161x; 1.1163x over previous
#include <cuda_runtime.h>

// SparseTopKLayer: out = x + ((x*rms)*w)*mask*gamma
//   rms = rsqrt(mean(x^2)+1e-6); mask = |x_norm| >= kth_largest(|x_norm|, k)
// Rank on |x*w| (rms>0 row-constant -> identical ordering).
// One CTA per row, 256 threads, 8 elems/thread in registers.
// Gaussian-quantile window + single fused histogram pass (above-count folded
// in), adaptive re-window loop keeps it exact for arbitrary data.

constexpr int D    = 2048;
constexpr int T    = 256;
constexpr int BINS = 128;

__device__ __forceinline__ float inv_phi_tail(float q) {
    // Phi^{-1}(1-q), q in (0, 0.5]; Abramowitz-Stegun 26.2.23, |err|<4.5e-4
    q = fminf(fmaxf(q, 1e-7f), 0.4999f);
    float s = sqrtf(-2.0f * __logf(q));
    return s - (2.30753f + 0.27061f * s) / (1.0f + s * (0.99229f + 0.04481f * s));
}

__global__ void __launch_bounds__(T, 6) sparse_topk_kernel(
    const float* __restrict__ x,
    const float* __restrict__ w,
    const float* __restrict__ g,
    const int* __restrict__ kptr,
    float* __restrict__ out)
{
    const int row  = blockIdx.x;
    const int t    = threadIdx.x;
    const int lane = t & 31;
    const int wid  = t >> 5;

    __shared__ float2   red[8];
    __shared__ __align__(16) unsigned hist[2][BINS];
    __shared__ unsigned lo_sh, hi_sh, thr_sh, thrmin_sh, thrmax_sh, above_sh;
    __shared__ int      r_sh, mode_sh;
    __shared__ float    rms_sh;

    // ---- load row + weight, xw = x*w, dual sums ----
    const float4* xr = reinterpret_cast<const float4*>(x) + (size_t)row * (D / 4);
    const float4* wv = reinterpret_cast<const float4*>(w);
    float4 xa = xr[t], xb = xr[t + T];
    float4 wa = wv[t], wb = wv[t + T];

    float xv[8] = {xa.x, xa.y, xa.z, xa.w, xb.x, xb.y, xb.z, xb.w};
    float xw[8];
    {
        float wf[8] = {wa.x, wa.y, wa.z, wa.w, wb.x, wb.y, wb.z, wb.w};
        #pragma unroll
        for (int i = 0; i < 8; i++) xw[i] = xv[i] * wf[i];
    }
    float ss = 0.0f, sw = 0.0f;
    #pragma unroll
    for (int i = 0; i < 8; i++) {
        ss = fmaf(xv[i], xv[i], ss);
        sw = fmaf(xw[i], xw[i], sw);
    }
    #pragma unroll
    for (int o = 16; o > 0; o >>= 1) {
        ss += __shfl_xor_sync(0xffffffffu, ss, o);
        sw += __shfl_xor_sync(0xffffffffu, sw, o);
    }
    if (lane == 0) red[wid] = make_float2(ss, sw);
    ((unsigned*)hist)[t] = 0u;                       // zero both buffers
    if (t == 0) { above_sh = 0u; thrmin_sh = 0xFFFFFFFFu; thrmax_sh = 0u; }
    __syncthreads();

    // ---- warp0: rms + Gaussian-quantile window ----
    if (t < 8) {
        float2 v = red[t];
        #pragma unroll
        for (int o = 4; o > 0; o >>= 1) {
            v.x += __shfl_xor_sync(0xffu, v.x, o);
            v.y += __shfl_xor_sync(0xffu, v.y, o);
        }
        if (t == 0) {
            rms_sh = rsqrtf(v.x * (1.0f / (float)D) + 1e-6f);
            float sigma = sqrtf(v.y * (1.0f / (float)D));
            int k = *kptr;
            float t1 = inv_phi_tail((float)(k + 64) * (0.5f / (float)D));
            float t2 = inv_phi_tail((float)(k - 64 > 1 ? k - 64 : 1) * (0.5f / (float)D));
            unsigned b1 = (t1 > 0.0f) ? __float_as_uint(t1 * sigma) : 0u;
            unsigned b2 = __float_as_uint(fmaxf(t2, 0.0f) * sigma);
            if (b2 <= b1) b2 = b1 + 1u;
            lo_sh = b1; hi_sh = b2; r_sh = k; mode_sh = 0;
        }
    }
    __syncthreads();

    // ---- adaptive-window histogram select (exact) ----
    unsigned thr = 0u;
    int p = 0, round = 0;
    while (true) {
        const unsigned lo = lo_sh, hi = hi_sh;
        const unsigned range = hi - lo;
        const int s = (range > (unsigned)BINS) ? (25 - __clz(range - 1u)) : 0;
        unsigned* h = hist[p];
        unsigned above = 0u;
        #pragma unroll
        for (int i = 0; i < 8; i++) {
            unsigned ub = __float_as_uint(fabsf(xw[i]));
            unsigned d = ub - lo;
            if (d < range) atomicAdd(&h[d >> s], 1u);
            if (round == 0) above += (ub >= hi);
        }
        if (round == 0) {
            above = __reduce_add_sync(0xffffffffu, above);
            if (lane == 0) atomicAdd(&above_sh, above);
        }
        if (t < BINS) hist[p ^ 1][t] = 0u;           // prep next buffer
        __syncthreads();

        if (t < 32) {   // warp0: suffix scan + classify + publish
            uint4 hv = *reinterpret_cast<const uint4*>(&h[lane * 4]);
            unsigned hr[4] = {hv.x, hv.y, hv.z, hv.w};
            unsigned bs = hr[0] + hr[1] + hr[2] + hr[3];
            unsigned S = bs;
            #pragma unroll
            for (int o = 1; o < 32; o <<= 1) {
                unsigned v = __shfl_down_sync(0xffffffffu, S, o);
                if (lane + o < 32) S += v;
            }
            unsigned total = __shfl_sync(0xffffffffu, S, 0);
            int r = r_sh;
            if (round == 0) r -= (int)above_sh;

            if (r <= 0) {                 // threshold above window
                if (lane == 0) { lo_sh = hi; hi_sh = 0x80000000u;
                                 r_sh = r + (int)above_sh; mode_sh = 0; }
            } else if ((unsigned)r > total) {   // threshold below window
                if (lane == 0) { hi_sh = lo; lo_sh = 0u;
                                 r_sh = r - (int)total; mode_sh = 0; }
            } else {
                unsigned suf = S - bs;    // count in strictly-higher lanes
                int bj = -1; unsigned cnt = 0, abv = 0;
                #pragma unroll
                for (int j = 3; j >= 0; j--) {
                    unsigned ns = suf + hr[j];
                    if (suf < (unsigned)r && ns >= (unsigned)r) { bj = j; cnt = hr[j]; abv = suf; }
                    suf = ns;
                }
                unsigned bal = __ballot_sync(0xffffffffu, bj >= 0);
                int src = __ffs(bal) - 1;
                unsigned B = __shfl_sync(0xffffffffu, (unsigned)(lane * 4 + bj), src);
                cnt = __shfl_sync(0xffffffffu, cnt, src);
                abv = __shfl_sync(0xffffffffu, abv, src);
                if (lane == 0) {
                    int r2 = r - (int)abv;
                    unsigned nlo = lo + (B << s);
                    unsigned nhi = lo + ((B + 1u) << s);
                    if (nhi > hi) nhi = hi;
                    lo_sh = nlo; hi_sh = nhi; r_sh = r2;
                    if (s == 0)              { mode_sh = 1; thr_sh = nlo; }
                    else if ((int)cnt == r2) { mode_sh = 2; }  // thr = min in bucket
                    else if (r2 == 1)        { mode_sh = 3; }  // thr = max in bucket
                    else                     { mode_sh = 0; }
                }
            }
        }
        __syncthreads();

        int m = mode_sh;
        if (m == 1) { thr = thr_sh; break; }
        if (m >= 2) {
            const unsigned nlo = lo_sh, nrange = hi_sh - lo_sh;
            if (m == 2) {
                unsigned lm = 0xFFFFFFFFu;
                #pragma unroll
                for (int i = 0; i < 8; i++) {
                    unsigned ub = __float_as_uint(fabsf(xw[i]));
                    if (ub - nlo < nrange) lm = min(lm, ub);
                }
                lm = __reduce_min_sync(0xffffffffu, lm);
                if (lane == 0) atomicMin(&thrmin_sh, lm);
            } else {
                unsigned lm = 0u;
                #pragma unroll
                for (int i = 0; i < 8; i++) {
                    unsigned ub = __float_as_uint(fabsf(xw[i]));
                    if (ub - nlo < nrange) lm = max(lm, ub);
                }
                lm = __reduce_max_sync(0xffffffffu, lm);
                if (lane == 0) atomicMax(&thrmax_sh, lm);
            }
            __syncthreads();
            thr = (m == 2) ? thrmin_sh : thrmax_sh;
            break;
        }
        p ^= 1; round++;
    }

    // ---- epilogue: out = x + (xw*rms)*g where |xw| >= thr ----
    const float4* gv = reinterpret_cast<const float4*>(g);
    float4 ga = gv[t], gb = gv[t + T];
    float gf[8] = {ga.x, ga.y, ga.z, ga.w, gb.x, gb.y, gb.z, gb.w};
    const float rms  = rms_sh;
    const float thrf = __uint_as_float(thr);

    float fo[8];
    #pragma unroll
    for (int i = 0; i < 8; i++) {
        float add = (xw[i] * rms) * gf[i];
        fo[i] = xv[i] + ((fabsf(xw[i]) >= thrf) ? add : 0.0f);
    }
    float4* orow = reinterpret_cast<float4*>(out) + (size_t)row * (D / 4);
    orow[t]     = make_float4(fo[0], fo[1], fo[2], fo[3]);
    orow[t + T] = make_float4(fo[4], fo[5], fo[6], fo[7]);
}

extern "C" void kernel_launch(void* const* d_in, const int* in_sizes, int n_in,
                              void* d_out, int out_size)
{
    const float* x = (const float*)d_in[0];
    const float* w = (const float*)d_in[1];
    const float* g = (const float*)d_in[2];
    const int*   k = (const int*)d_in[3];

    int N = in_sizes[0] / D;   // 32768 rows
    sparse_topk_kernel<<<N, T>>>(x, w, g, k, (float*)d_out);
}